// round 1
// baseline (speedup 1.0000x reference)
#include <cuda_runtime.h>

// out[n][d] = (x[n]==0 ? 0 : W[x[n]][d]) + PE(n,d)
// PE(n,d): pos = n+1 (1-based); even d -> cos(pos * 10000^{-d/D});
//          odd d  -> sin(pos * 10000^{-(d+1)/D})
// Note odd j=2k+1 and even j=2k+2 share the same frequency 10000^{-(2k+2)/D},
// so a thread covering 4 consecutive d's needs only 3 (sin,cos) states.
//
// Hot loop is trig-free: the PE advances across rows by a fixed FMA rotation
// (ang -> ang + w). States are re-seeded exactly (double precision) at the top
// of each 128-row chunk, bounding drift to ~3e-5 absolute.

#define D_DIM  1024
#define TPB    256      // D/4: one float4 per thread per row
#define ROWS   128      // rows per block (recurrence length; drift ~3e-5)

__global__ __launch_bounds__(TPB)
void pe_embed_kernel(const int* __restrict__ x,
                     const float* __restrict__ W,
                     float* __restrict__ out,
                     int N)
{
    __shared__ int sx[ROWS];

    const int n0 = blockIdx.x * ROWS;
    const int t  = threadIdx.x;

    // Stage the row indices once; removes a per-iteration global-load chain.
    if (t < ROWS) {
        int n = n0 + t;
        sx[t] = (n < N) ? x[n] : 0;
    }

    // ---- seed the 3 rotation states for this thread's 4 d's ----
    // d = 4t+k. k=0 -> cos@e=d0 ; k=1 -> sin@e=d0+2 ; k=2 -> cos@e=d0+2 ; k=3 -> sin@e=d0+4
    const int d0 = t * 4;
    float s[3], c[3], sw[3], cw[3];
    const double LOG1E4  = 9.210340371976184;          // ln(10000)
    const double TWO_PI  = 6.283185307179586476925287;
    const double INV_2PI = 0.15915494309189533576888;
    const double pos0 = (double)(n0 + 1);
#pragma unroll
    for (int m = 0; m < 3; m++) {
        int e = d0 + 2 * m;
        double w = exp(-(double)e * (LOG1E4 / (double)D_DIM));
        double sws, cws;
        sincos(w, &sws, &cws);          // per-step rotation constants (exact-ish)
        sw[m] = (float)sws;
        cw[m] = (float)cws;
        double ang = pos0 * w;          // exact to ~1e-11 abs at this magnitude
        ang -= TWO_PI * floor(ang * INV_2PI);
        float a = (float)ang;
        s[m] = sinf(a);
        c[m] = cosf(a);
    }
    __syncthreads();

    const float4* __restrict__ Wv = (const float4*)W;
    float4* outv = (float4*)out;

    const int nr = (N - n0 < ROWS) ? (N - n0) : ROWS;
    const long obase = (long)n0 * (D_DIM / 4) + t;

#pragma unroll 4
    for (int r = 0; r < nr; r++) {
        int idx = sx[r];
        float4 e = make_float4(0.f, 0.f, 0.f, 0.f);
        if (idx != 0) {                 // padding_idx row contributes zero
            e = __ldg(&Wv[(long)idx * (D_DIM / 4) + t]);
        }
        float4 o;
        o.x = e.x + c[0];
        o.y = e.y + s[1];
        o.z = e.z + c[1];
        o.w = e.w + s[2];
        // streaming store: don't let the 512MB output evict W rows from L2
        __stcs(&outv[obase + (long)r * (D_DIM / 4)], o);

        // advance all three states by one row: (s,c) <- rot(w) * (s,c)
#pragma unroll
        for (int m = 0; m < 3; m++) {
            float ns = fmaf(s[m], cw[m],  c[m] * sw[m]);
            float nc = fmaf(c[m], cw[m], -s[m] * sw[m]);
            s[m] = ns;
            c[m] = nc;
        }
    }
}

extern "C" void kernel_launch(void* const* d_in, const int* in_sizes, int n_in,
                              void* d_out, int out_size)
{
    // x is the small int32 input (N elems), W the big float32 table (V*D).
    const int*   x;
    const float* W;
    int N;
    if (in_sizes[0] < in_sizes[1]) {
        x = (const int*)d_in[0];  W = (const float*)d_in[1];  N = in_sizes[0];
    } else {
        x = (const int*)d_in[1];  W = (const float*)d_in[0];  N = in_sizes[1];
    }
    int blocks = (N + ROWS - 1) / ROWS;
    pe_embed_kernel<<<blocks, TPB>>>(x, W, (float*)d_out, N);
}